// round 9
// baseline (speedup 1.0000x reference)
#include <cuda_runtime.h>
#include <cuda_bf16.h>
#include <cstdint>
#include <cstddef>

// Problem constants
#define Bq  4
#define Sq  2048
#define Dq  1024
#define Hq  16
#define HDq 64
#define Mq  (Bq * Sq)   // 8192

#define MD  ((size_t)Mq * Dq)

// Scratch (all bf16 hi/lo split pairs)
__device__ __nv_bfloat16 g_xh[MD];
__device__ __nv_bfloat16 g_xl[MD];
__device__ __nv_bfloat16 g_wh[(size_t)4 * Dq * Dq];   // wq|wk|wv|wo
__device__ __nv_bfloat16 g_wl[(size_t)4 * Dq * Dq];
__device__ __nv_bfloat16 g_qkvh[3 * MD];              // q|k|v
__device__ __nv_bfloat16 g_qkvl[3 * MD];
__device__ __nv_bfloat16 g_vth[MD];                   // [B,H,HD,S]
__device__ __nv_bfloat16 g_vtl[MD];
__device__ __nv_bfloat16 g_oh[MD];
__device__ __nv_bfloat16 g_ol[MD];
__device__ unsigned int  g_mbits[(size_t)Bq * Sq * (Sq / 32)];

// ---------------------------------------------------------------------------
// helpers
// ---------------------------------------------------------------------------
__device__ __forceinline__ void mma_bf16(float& d0, float& d1, float& d2, float& d3,
                                         uint32_t a0, uint32_t a1, uint32_t a2, uint32_t a3,
                                         uint32_t b0, uint32_t b1)
{
    asm volatile(
        "mma.sync.aligned.m16n8k16.row.col.f32.bf16.bf16.f32 "
        "{%0,%1,%2,%3}, {%4,%5,%6,%7}, {%8,%9}, {%0,%1,%2,%3};"
        : "+f"(d0), "+f"(d1), "+f"(d2), "+f"(d3)
        : "r"(a0), "r"(a1), "r"(a2), "r"(a3), "r"(b0), "r"(b1));
}

__device__ __forceinline__ void ldm_x4(uint32_t& r0, uint32_t& r1, uint32_t& r2, uint32_t& r3,
                                       uint32_t addr)
{
    asm volatile("ldmatrix.sync.aligned.m8n8.x4.shared.b16 {%0,%1,%2,%3}, [%4];"
                 : "=r"(r0), "=r"(r1), "=r"(r2), "=r"(r3) : "r"(addr));
}

__device__ __forceinline__ uint32_t pack_bf16(float e0, float e1)
{
    __nv_bfloat162 t = __floats2bfloat162_rn(e0, e1);
    return *(uint32_t*)&t;
}

__device__ __forceinline__ void cpa16(uint32_t saddr, const void* gptr)
{
    asm volatile("cp.async.cg.shared.global [%0], [%1], 16;" :: "r"(saddr), "l"(gptr));
}
__device__ __forceinline__ void cpa_commit() { asm volatile("cp.async.commit_group;"); }
template<int N> __device__ __forceinline__ void cpa_wait()
{ asm volatile("cp.async.wait_group %0;" :: "n"(N) : "memory"); }

// ---------------------------------------------------------------------------
// fp32 -> bf16 hi/lo split
// ---------------------------------------------------------------------------
__global__ __launch_bounds__(256) void split_f32(
    const float4* __restrict__ in,
    __nv_bfloat162* __restrict__ hi, __nv_bfloat162* __restrict__ lo)
{
    size_t i = (size_t)blockIdx.x * 256 + threadIdx.x;
    float4 v = in[i];
    __nv_bfloat162 h0 = __floats2bfloat162_rn(v.x, v.y);
    __nv_bfloat162 h1 = __floats2bfloat162_rn(v.z, v.w);
    __nv_bfloat162 l0 = __floats2bfloat162_rn(v.x - __bfloat162float(h0.x),
                                              v.y - __bfloat162float(h0.y));
    __nv_bfloat162 l1 = __floats2bfloat162_rn(v.z - __bfloat162float(h1.x),
                                              v.w - __bfloat162float(h1.y));
    hi[i * 2]     = h0; hi[i * 2 + 1] = h1;
    lo[i * 2]     = l0; lo[i * 2 + 1] = l1;
}

// ---------------------------------------------------------------------------
// Tensor-core NT GEMM, pre-split bf16 hi/lo, cp.async double-buffer.
// BM=128, BN=256, BK=32; 8 warps as 2x4 -> warp tile 64x64 (mma:ldm = 6:1).
// BF16OUT epilogue routes each 1024-col matrix slice to its own hi/lo buffer
// (used for fused QKV with N=3072). Float path writes C[M,N].
// ---------------------------------------------------------------------------
#define GP2B    80                    // row pitch bytes (40 bf16)
#define A_BYTES (128 * GP2B)          // 10240
#define W_BYTES (256 * GP2B)          // 20480
#define GSTG    (2 * A_BYTES + 2 * W_BYTES)   // 61440
#define GEMM_SMEM (2 * GSTG)          // 122880

template<bool BF16OUT>
__global__ __launch_bounds__(256, 1) void gemm_nt_bf(
    const __nv_bfloat16* __restrict__ Ahg, const __nv_bfloat16* __restrict__ Alg,
    const __nv_bfloat16* __restrict__ Whg, const __nv_bfloat16* __restrict__ Wlg,
    float* __restrict__ C, __nv_bfloat16* __restrict__ Ch, __nv_bfloat16* __restrict__ Cl,
    int M, int N, int K)
{
    extern __shared__ char smg[];
    const uint32_t sbase = (uint32_t)__cvta_generic_to_shared(smg);

    const int tid  = threadIdx.x;
    const int wid  = tid >> 5;
    const int lane = tid & 31;
    const int wm = wid >> 2;          // 0..1 -> m offset 64*wm
    const int wn = wid & 3;           // 0..3 -> n offset 64*wn
    const int bm = blockIdx.y * 128;
    const int bn = blockIdx.x * 256;
    const int lm  = lane >> 3;
    const int lr  = lane & 7;

    float c[4][8][4];
    #pragma unroll
    for (int i = 0; i < 4; i++)
        #pragma unroll
        for (int j = 0; j < 8; j++)
            #pragma unroll
            for (int r = 0; r < 4; r++) c[i][j][r] = 0.f;

    auto issue = [&](int k0, int stg) {
        const uint32_t sb = sbase + (uint32_t)stg * GSTG;
        #pragma unroll
        for (int i = 0; i < 2; i++) {               // A: 512 chunks per array
            int ch  = i * 256 + tid;
            int row = ch >> 2;
            int c16 = ch & 3;
            uint32_t so = sb + row * GP2B + c16 * 16;
            size_t ga = (size_t)(bm + row) * K + k0 + c16 * 8;
            cpa16(so,           Ahg + ga);
            cpa16(so + A_BYTES, Alg + ga);
        }
        #pragma unroll
        for (int i = 0; i < 4; i++) {               // W: 1024 chunks per array
            int ch  = i * 256 + tid;
            int row = ch >> 2;
            int c16 = ch & 3;
            uint32_t so = sb + 2 * A_BYTES + row * GP2B + c16 * 16;
            size_t gw = (size_t)(bn + row) * K + k0 + c16 * 8;
            cpa16(so,           Whg + gw);
            cpa16(so + W_BYTES, Wlg + gw);
        }
        cpa_commit();
    };

    issue(0, 0);
    const int T = K / 32;
    for (int t = 0; t < T; t++) {
        if (t + 1 < T) { issue((t + 1) * 32, (t + 1) & 1); cpa_wait<1>(); }
        else           { cpa_wait<0>(); }
        __syncthreads();

        const uint32_t sb = sbase + (uint32_t)(t & 1) * GSTG;
        const uint32_t wb = sb + 2 * A_BYTES;

        #pragma unroll
        for (int ks = 0; ks < 2; ks++) {
            const int a_row_in16 = lr + ((lm & 1) << 3);
            const int a_kbyte    = ks * 32 + ((lm >> 1) << 4);

            uint32_t a_hi[4][4], a_lo[4][4];
            #pragma unroll
            for (int mt = 0; mt < 4; mt++) {
                uint32_t off = (uint32_t)((wm * 64 + mt * 16 + a_row_in16) * GP2B) + a_kbyte;
                ldm_x4(a_hi[mt][0], a_hi[mt][1], a_hi[mt][2], a_hi[mt][3], sb + off);
                ldm_x4(a_lo[mt][0], a_lo[mt][1], a_lo[mt][2], a_lo[mt][3], sb + A_BYTES + off);
            }

            #pragma unroll
            for (int p = 0; p < 4; p++) {           // n-tile pair {2p, 2p+1}
                int ntile = p * 2 + (lm >> 1);
                int n_row = wn * 64 + ntile * 8 + lr;
                uint32_t off = (uint32_t)(n_row * GP2B) + (uint32_t)(ks * 32 + ((lm & 1) << 4));
                uint32_t bh0, bh1, bh2, bh3, bl0, bl1, bl2, bl3;
                ldm_x4(bh0, bh1, bh2, bh3, wb + off);
                ldm_x4(bl0, bl1, bl2, bl3, wb + W_BYTES + off);
                int n0 = p * 2, n1 = p * 2 + 1;
                #pragma unroll
                for (int mt = 0; mt < 4; mt++) {
                    mma_bf16(c[mt][n0][0], c[mt][n0][1], c[mt][n0][2], c[mt][n0][3],
                             a_hi[mt][0], a_hi[mt][1], a_hi[mt][2], a_hi[mt][3], bh0, bh1);
                    mma_bf16(c[mt][n1][0], c[mt][n1][1], c[mt][n1][2], c[mt][n1][3],
                             a_hi[mt][0], a_hi[mt][1], a_hi[mt][2], a_hi[mt][3], bh2, bh3);
                    mma_bf16(c[mt][n0][0], c[mt][n0][1], c[mt][n0][2], c[mt][n0][3],
                             a_hi[mt][0], a_hi[mt][1], a_hi[mt][2], a_hi[mt][3], bl0, bl1);
                    mma_bf16(c[mt][n1][0], c[mt][n1][1], c[mt][n1][2], c[mt][n1][3],
                             a_hi[mt][0], a_hi[mt][1], a_hi[mt][2], a_hi[mt][3], bl2, bl3);
                    mma_bf16(c[mt][n0][0], c[mt][n0][1], c[mt][n0][2], c[mt][n0][3],
                             a_lo[mt][0], a_lo[mt][1], a_lo[mt][2], a_lo[mt][3], bh0, bh1);
                    mma_bf16(c[mt][n1][0], c[mt][n1][1], c[mt][n1][2], c[mt][n1][3],
                             a_lo[mt][0], a_lo[mt][1], a_lo[mt][2], a_lo[mt][3], bh2, bh3);
                }
            }
        }
        __syncthreads();
    }

    const int g  = lane >> 2;
    const int t2 = lane & 3;
    #pragma unroll
    for (int mt = 0; mt < 4; mt++) {
        #pragma unroll
        for (int nt = 0; nt < 8; nt++) {
            int row0 = bm + wm * 64 + mt * 16 + g;
            int gcol = bn + wn * 64 + nt * 8 + t2 * 2;
            if (BF16OUT) {
                int sel  = gcol >> 10;              // which 1024-col output matrix
                int colL = gcol & 1023;
                #pragma unroll
                for (int half = 0; half < 2; half++) {
                    float v0 = c[mt][nt][half * 2], v1 = c[mt][nt][half * 2 + 1];
                    __nv_bfloat162 hi = __floats2bfloat162_rn(v0, v1);
                    __nv_bfloat162 lo = __floats2bfloat162_rn(v0 - __bfloat162float(hi.x),
                                                              v1 - __bfloat162float(hi.y));
                    size_t off = ((size_t)sel * Mq + row0 + half * 8) * Dq + colL;
                    *(__nv_bfloat162*)(Ch + off) = hi;
                    *(__nv_bfloat162*)(Cl + off) = lo;
                }
            } else {
                *(float2*)(C + (size_t)row0 * N + gcol)       = make_float2(c[mt][nt][0], c[mt][nt][1]);
                *(float2*)(C + (size_t)(row0 + 8) * N + gcol) = make_float2(c[mt][nt][2], c[mt][nt][3]);
            }
        }
    }
}

// ---------------------------------------------------------------------------
// V transpose: [B,S,D] bf16 (per head [s][hd]) -> [B,H,HD,S]
// ---------------------------------------------------------------------------
__global__ __launch_bounds__(256) void transpose_v(
    const __nv_bfloat16* __restrict__ vh, const __nv_bfloat16* __restrict__ vl,
    __nv_bfloat16* __restrict__ vth, __nv_bfloat16* __restrict__ vtl)
{
    __shared__ __nv_bfloat16 th[64 * 72];
    __shared__ __nv_bfloat16 tl[64 * 72];
    const int tid = threadIdx.x;
    const int bh = blockIdx.y;
    const int b = bh >> 4, h = bh & 15;
    const int s0 = blockIdx.x * 64;

    const size_t src = (size_t)(b * Sq + s0) * Dq + h * HDq;
    #pragma unroll
    for (int i = 0; i < 2; i++) {
        int chunk = i * 256 + tid;
        int r = chunk >> 3, cc = chunk & 7;
        *(uint4*)&th[r * 72 + cc * 8] = *(const uint4*)(vh + src + (size_t)r * Dq + cc * 8);
        *(uint4*)&tl[r * 72 + cc * 8] = *(const uint4*)(vl + src + (size_t)r * Dq + cc * 8);
    }
    __syncthreads();

    const size_t dst = (size_t)bh * HDq * Sq + s0;
    #pragma unroll
    for (int i = 0; i < 2; i++) {
        int chunk = i * 256 + tid;
        int r = chunk >> 3, cc = chunk & 7;
        alignas(16) __nv_bfloat16 tmpH[8];
        alignas(16) __nv_bfloat16 tmpL[8];
        #pragma unroll
        for (int e = 0; e < 8; e++) {
            tmpH[e] = th[(cc * 8 + e) * 72 + r];
            tmpL[e] = tl[(cc * 8 + e) * 72 + r];
        }
        *(uint4*)(vth + dst + (size_t)r * Sq + cc * 8) = *(uint4*)tmpH;
        *(uint4*)(vtl + dst + (size_t)r * Sq + cc * 8) = *(uint4*)tmpL;
    }
}

// ---------------------------------------------------------------------------
// Mask pack
// ---------------------------------------------------------------------------
__global__ __launch_bounds__(256) void pack_mask(
    const unsigned int* __restrict__ mask, unsigned int* __restrict__ mbits)
{
    int w = blockIdx.x * 256 + threadIdx.x;
    size_t row = (size_t)(w >> 6);
    int wi = w & 63;
    const uint4* p = (const uint4*)(mask + row * Sq + wi * 32);
    unsigned int bits = 0;
    #pragma unroll
    for (int i = 0; i < 8; i++) {
        uint4 m = p[i];
        bits |= (unsigned)(m.x != 0u) << (4 * i + 0);
        bits |= (unsigned)(m.y != 0u) << (4 * i + 1);
        bits |= (unsigned)(m.z != 0u) << (4 * i + 2);
        bits |= (unsigned)(m.w != 0u) << (4 * i + 3);
    }
    mbits[w] = bits;
}

// ---------------------------------------------------------------------------
// Tensor-core flash attention (unchanged from R8).
// ---------------------------------------------------------------------------
#define APB    144
#define REG9   9216
#define STAGEB (4 * REG9)
#define ATTN_SMEM (2 * STAGEB)

__global__ __launch_bounds__(256, 2) void attn_tc(
    const __nv_bfloat16* __restrict__ Qhg, const __nv_bfloat16* __restrict__ Qlg,
    const __nv_bfloat16* __restrict__ Khg, const __nv_bfloat16* __restrict__ Klg,
    const __nv_bfloat16* __restrict__ Vthg, const __nv_bfloat16* __restrict__ Vtlg,
    const unsigned int* __restrict__ mbits,
    __nv_bfloat16* __restrict__ Ohg, __nv_bfloat16* __restrict__ Olg)
{
    extern __shared__ char smem[];
    const uint32_t sbase = (uint32_t)__cvta_generic_to_shared(smem);

    const int tid  = threadIdx.x;
    const int wid  = tid >> 5;
    const int lane = tid & 31;
    const int lm   = lane >> 3;
    const int lr   = lane & 7;
    const int g    = lane >> 2;
    const int t2   = lane & 3;

    const int bh = blockIdx.y;
    const int b  = bh >> 4;
    const int h  = bh & 15;
    const int q0 = blockIdx.x * 128;

    const size_t qrow0 = (size_t)(b * Sq + q0) * Dq + h * HDq;
    #pragma unroll
    for (int i = 0; i < 4; i++) {
        int chunk = i * 256 + tid;
        int r = chunk >> 3, cc = chunk & 7;
        uint32_t so = sbase + r * APB + cc * 16;
        cpa16(so,         Qhg + qrow0 + (size_t)r * Dq + cc * 8);
        cpa16(so + 18432, Qlg + qrow0 + (size_t)r * Dq + cc * 8);
    }
    cpa_commit();
    cpa_wait<0>();
    __syncthreads();

    uint32_t qa_h[4][4], qa_l[4][4];
    {
        const int a_row = wid * 16 + lr + ((lm & 1) << 3);
        #pragma unroll
        for (int ks = 0; ks < 4; ks++) {
            uint32_t off = (uint32_t)(a_row * APB) + (uint32_t)(ks * 32 + ((lm >> 1) << 4));
            ldm_x4(qa_h[ks][0], qa_h[ks][1], qa_h[ks][2], qa_h[ks][3], sbase + off);
            ldm_x4(qa_l[ks][0], qa_l[ks][1], qa_l[ks][2], qa_l[ks][3], sbase + 18432 + off);
        }
    }
    __syncthreads();

    float o_acc[8][4];
    #pragma unroll
    for (int j = 0; j < 8; j++)
        #pragma unroll
        for (int r = 0; r < 4; r++) o_acc[j][r] = 0.f;
    float m0 = -1e30f, m1 = -1e30f, l0 = 0.f, l1 = 0.f;

    const size_t kbase  = (size_t)(b * Sq) * Dq + h * HDq;
    const size_t vtbase = (size_t)bh * HDq * Sq;
    const size_t mrow   = ((size_t)b * Sq + q0) * 64;
    const int r0 = wid * 16 + g;
    const int r1 = r0 + 8;

    {
        const uint32_t sb = sbase;
        #pragma unroll
        for (int i = 0; i < 2; i++) {
            int chunk = i * 256 + tid;
            int r = chunk >> 3, cc = chunk & 7;
            uint32_t so = sb + r * APB + cc * 16;
            size_t kq = kbase + (size_t)r * Dq + cc * 8;
            size_t vq = vtbase + (size_t)r * Sq + cc * 8;
            cpa16(so,             Khg + kq);
            cpa16(so + REG9,      Klg + kq);
            cpa16(so + 2 * REG9,  Vthg + vq);
            cpa16(so + 3 * REG9,  Vtlg + vq);
        }
        cpa_commit();
    }

    for (int t = 0; t < Sq / 64; t++) {
        const int kb = t * 64;
        __syncthreads();
        if (t + 1 < Sq / 64) {
            const uint32_t sb = sbase + (uint32_t)((t + 1) & 1) * STAGEB;
            const int kb2 = kb + 64;
            #pragma unroll
            for (int i = 0; i < 2; i++) {
                int chunk = i * 256 + tid;
                int r = chunk >> 3, cc = chunk & 7;
                uint32_t so = sb + r * APB + cc * 16;
                size_t kq = kbase + (size_t)(kb2 + r) * Dq + cc * 8;
                size_t vq = vtbase + (size_t)r * Sq + kb2 + cc * 8;
                cpa16(so,             Khg + kq);
                cpa16(so + REG9,      Klg + kq);
                cpa16(so + 2 * REG9,  Vthg + vq);
                cpa16(so + 3 * REG9,  Vtlg + vq);
            }
            cpa_commit();
            cpa_wait<1>();
        } else {
            cpa_wait<0>();
        }
        __syncthreads();

        const uint32_t kbuf = sbase + (uint32_t)(t & 1) * STAGEB;

        const uint2 mwA = *(const uint2*)(mbits + mrow + (size_t)r0 * 64 + (kb >> 5));
        const uint2 mwB = *(const uint2*)(mbits + mrow + (size_t)r1 * 64 + (kb >> 5));

        float s[8][4];
        #pragma unroll
        for (int j = 0; j < 8; j++)
            #pragma unroll
            for (int r = 0; r < 4; r++) s[j][r] = 0.f;

        #pragma unroll
        for (int ks = 0; ks < 4; ks++) {
            #pragma unroll
            for (int p2 = 0; p2 < 4; p2++) {
                int ntile = p2 * 2 + (lm >> 1);
                uint32_t off = (uint32_t)((ntile * 8 + lr) * APB)
                             + (uint32_t)(ks * 32 + ((lm & 1) << 4));
                uint32_t bh0, bh1, bh2, bh3, bl0, bl1, bl2, bl3;
                ldm_x4(bh0, bh1, bh2, bh3, kbuf + off);
                ldm_x4(bl0, bl1, bl2, bl3, kbuf + REG9 + off);
                int n0 = p2 * 2, n1 = p2 * 2 + 1;
                mma_bf16(s[n0][0], s[n0][1], s[n0][2], s[n0][3],
                         qa_h[ks][0], qa_h[ks][1], qa_h[ks][2], qa_h[ks][3], bh0, bh1);
                mma_bf16(s[n1][0], s[n1][1], s[n1][2], s[n1][3],
                         qa_h[ks][0], qa_h[ks][1], qa_h[ks][2], qa_h[ks][3], bh2, bh3);
                mma_bf16(s[n0][0], s[n0][1], s[n0][2], s[n0][3],
                         qa_h[ks][0], qa_h[ks][1], qa_h[ks][2], qa_h[ks][3], bl0, bl1);
                mma_bf16(s[n1][0], s[n1][1], s[n1][2], s[n1][3],
                         qa_h[ks][0], qa_h[ks][1], qa_h[ks][2], qa_h[ks][3], bl2, bl3);
                mma_bf16(s[n0][0], s[n0][1], s[n0][2], s[n0][3],
                         qa_l[ks][0], qa_l[ks][1], qa_l[ks][2], qa_l[ks][3], bh0, bh1);
                mma_bf16(s[n1][0], s[n1][1], s[n1][2], s[n1][3],
                         qa_l[ks][0], qa_l[ks][1], qa_l[ks][2], qa_l[ks][3], bh2, bh3);
            }
        }

        {
            unsigned int w0 = mwA.x, w1 = mwA.y;
            unsigned int x0 = mwB.x, x1 = mwB.y;
            float rmax0 = -1e30f, rmax1 = -1e30f;
            #pragma unroll
            for (int j = 0; j < 8; j++) {
                unsigned int wr0 = (j < 4) ? w0 : w1;
                unsigned int wr1 = (j < 4) ? x0 : x1;
                int sh = ((j & 3) * 8) + t2 * 2;
                bool k00 = (wr0 >> sh) & 1, k01 = (wr0 >> (sh + 1)) & 1;
                bool k10 = (wr1 >> sh) & 1, k11 = (wr1 >> (sh + 1)) & 1;
                s[j][0] = k00 ? s[j][0] * 0.125f : -1e30f;
                s[j][1] = k01 ? s[j][1] * 0.125f : -1e30f;
                s[j][2] = k10 ? s[j][2] * 0.125f : -1e30f;
                s[j][3] = k11 ? s[j][3] * 0.125f : -1e30f;
                rmax0 = fmaxf(rmax0, fmaxf(s[j][0], s[j][1]));
                rmax1 = fmaxf(rmax1, fmaxf(s[j][2], s[j][3]));
            }
            rmax0 = fmaxf(rmax0, __shfl_xor_sync(0xffffffffu, rmax0, 1));
            rmax0 = fmaxf(rmax0, __shfl_xor_sync(0xffffffffu, rmax0, 2));
            rmax1 = fmaxf(rmax1, __shfl_xor_sync(0xffffffffu, rmax1, 1));
            rmax1 = fmaxf(rmax1, __shfl_xor_sync(0xffffffffu, rmax1, 2));

            float mn0 = fmaxf(m0, rmax0);
            float mn1 = fmaxf(m1, rmax1);
            float rs0 = 0.f, rs1 = 0.f;
            #pragma unroll
            for (int j = 0; j < 8; j++) {
                s[j][0] = (s[j][0] > -1e29f) ? __expf(s[j][0] - mn0) : 0.f;
                s[j][1] = (s[j][1] > -1e29f) ? __expf(s[j][1] - mn0) : 0.f;
                s[j][2] = (s[j][2] > -1e29f) ? __expf(s[j][2] - mn1) : 0.f;
                s[j][3] = (s[j][3] > -1e29f) ? __expf(s[j][3] - mn1) : 0.f;
                rs0 += s[j][0] + s[j][1];
                rs1 += s[j][2] + s[j][3];
            }
            rs0 += __shfl_xor_sync(0xffffffffu, rs0, 1);
            rs0 += __shfl_xor_sync(0xffffffffu, rs0, 2);
            rs1 += __shfl_xor_sync(0xffffffffu, rs1, 1);
            rs1 += __shfl_xor_sync(0xffffffffu, rs1, 2);

            float al0 = __expf(m0 - mn0);
            float al1 = __expf(m1 - mn1);
            l0 = l0 * al0 + rs0; m0 = mn0;
            l1 = l1 * al1 + rs1; m1 = mn1;
            #pragma unroll
            for (int j = 0; j < 8; j++) {
                o_acc[j][0] *= al0; o_acc[j][1] *= al0;
                o_acc[j][2] *= al1; o_acc[j][3] *= al1;
            }
        }

        #pragma unroll
        for (int kk = 0; kk < 4; kk++) {
            int ja = 2 * kk, jb = 2 * kk + 1;
            uint32_t pah[4], pal[4];
            {
                uint32_t h0 = pack_bf16(s[ja][0], s[ja][1]);
                uint32_t h1 = pack_bf16(s[ja][2], s[ja][3]);
                uint32_t h2 = pack_bf16(s[jb][0], s[jb][1]);
                uint32_t h3 = pack_bf16(s[jb][2], s[jb][3]);
                pah[0] = h0; pah[1] = h1; pah[2] = h2; pah[3] = h3;
                __nv_bfloat162 u;
                u = *(__nv_bfloat162*)&h0;
                pal[0] = pack_bf16(s[ja][0] - __bfloat162float(u.x), s[ja][1] - __bfloat162float(u.y));
                u = *(__nv_bfloat162*)&h1;
                pal[1] = pack_bf16(s[ja][2] - __bfloat162float(u.x), s[ja][3] - __bfloat162float(u.y));
                u = *(__nv_bfloat162*)&h2;
                pal[2] = pack_bf16(s[jb][0] - __bfloat162float(u.x), s[jb][1] - __bfloat162float(u.y));
                u = *(__nv_bfloat162*)&h3;
                pal[3] = pack_bf16(s[jb][2] - __bfloat162float(u.x), s[jb][3] - __bfloat162float(u.y));
            }
            #pragma unroll
            for (int p2 = 0; p2 < 4; p2++) {
                int ntile = p2 * 2 + (lm >> 1);
                uint32_t off = (uint32_t)((ntile * 8 + lr) * APB)
                             + (uint32_t)(kk * 32 + ((lm & 1) << 4));
                uint32_t bh0, bh1, bh2, bh3, bl0, bl1, bl2, bl3;
                ldm_x4(bh0, bh1, bh2, bh3, kbuf + 2 * REG9 + off);
                ldm_x4(bl0, bl1, bl2, bl3, kbuf + 3 * REG9 + off);
                int n0 = p2 * 2, n1 = p2 * 2 + 1;
                mma_bf16(o_acc[n0][0], o_acc[n0][1], o_acc[n0][2], o_acc[n0][3],
                         pah[0], pah[1], pah[2], pah[3], bh0, bh1);
                mma_bf16(o_acc[n1][0], o_acc[n1][1], o_acc[n1][2], o_acc[n1][3],
                         pah[0], pah[1], pah[2], pah[3], bh2, bh3);
                mma_bf16(o_acc[n0][0], o_acc[n0][1], o_acc[n0][2], o_acc[n0][3],
                         pah[0], pah[1], pah[2], pah[3], bl0, bl1);
                mma_bf16(o_acc[n1][0], o_acc[n1][1], o_acc[n1][2], o_acc[n1][3],
                         pah[0], pah[1], pah[2], pah[3], bl2, bl3);
                mma_bf16(o_acc[n0][0], o_acc[n0][1], o_acc[n0][2], o_acc[n0][3],
                         pal[0], pal[1], pal[2], pal[3], bh0, bh1);
                mma_bf16(o_acc[n1][0], o_acc[n1][1], o_acc[n1][2], o_acc[n1][3],
                         pal[0], pal[1], pal[2], pal[3], bh2, bh3);
            }
        }
    }

    const float inv0 = l0 > 0.f ? 1.f / l0 : 0.f;
    const float inv1 = l1 > 0.f ? 1.f / l1 : 0.f;
    const size_t obase = (size_t)b * Sq * Dq + (size_t)h * HDq;
    const int row0 = q0 + wid * 16 + g;
    #pragma unroll
    for (int j = 0; j < 8; j++) {
        int col = j * 8 + t2 * 2;
        #pragma unroll
        for (int half = 0; half < 2; half++) {
            float v0 = (half ? o_acc[j][2] * inv1 : o_acc[j][0] * inv0);
            float v1 = (half ? o_acc[j][3] * inv1 : o_acc[j][1] * inv0);
            __nv_bfloat162 hv = __floats2bfloat162_rn(v0, v1);
            __nv_bfloat162 lv = __floats2bfloat162_rn(v0 - __bfloat162float(hv.x),
                                                      v1 - __bfloat162float(hv.y));
            size_t off = obase + (size_t)(row0 + half * 8) * Dq + col;
            *(__nv_bfloat162*)(Ohg + off) = hv;
            *(__nv_bfloat162*)(Olg + off) = lv;
        }
    }
}

// ---------------------------------------------------------------------------
// Launch
// ---------------------------------------------------------------------------
extern "C" void kernel_launch(void* const* d_in, const int* in_sizes, int n_in,
                              void* d_out, int out_size)
{
    const float* x  = (const float*)d_in[0];
    const unsigned int* mask = (const unsigned int*)d_in[1];
    const float* wq = (const float*)d_in[2];
    const float* wk = (const float*)d_in[3];
    const float* wv = (const float*)d_in[4];
    const float* wo = (const float*)d_in[5];
    float* out = (float*)d_out;

    __nv_bfloat16 *xh, *xl, *wh, *wl, *qkvh, *qkvl, *vth, *vtl, *oh, *ol;
    unsigned int* mbits;
    cudaGetSymbolAddress((void**)&xh,   g_xh);
    cudaGetSymbolAddress((void**)&xl,   g_xl);
    cudaGetSymbolAddress((void**)&wh,   g_wh);
    cudaGetSymbolAddress((void**)&wl,   g_wl);
    cudaGetSymbolAddress((void**)&qkvh, g_qkvh);
    cudaGetSymbolAddress((void**)&qkvl, g_qkvl);
    cudaGetSymbolAddress((void**)&vth,  g_vth);
    cudaGetSymbolAddress((void**)&vtl,  g_vtl);
    cudaGetSymbolAddress((void**)&oh,   g_oh);
    cudaGetSymbolAddress((void**)&ol,   g_ol);
    cudaGetSymbolAddress((void**)&mbits, g_mbits);

    const size_t WSZ = (size_t)Dq * Dq;

    pack_mask<<<(Bq * Sq * (Sq / 32)) / 256, 256>>>(mask, mbits);
    split_f32<<<(Mq * Dq) / 1024, 256>>>((const float4*)x,
                                         (__nv_bfloat162*)xh, (__nv_bfloat162*)xl);
    split_f32<<<(Dq * Dq) / 1024, 256>>>((const float4*)wq,
                                         (__nv_bfloat162*)(wh + 0 * WSZ), (__nv_bfloat162*)(wl + 0 * WSZ));
    split_f32<<<(Dq * Dq) / 1024, 256>>>((const float4*)wk,
                                         (__nv_bfloat162*)(wh + 1 * WSZ), (__nv_bfloat162*)(wl + 1 * WSZ));
    split_f32<<<(Dq * Dq) / 1024, 256>>>((const float4*)wv,
                                         (__nv_bfloat162*)(wh + 2 * WSZ), (__nv_bfloat162*)(wl + 2 * WSZ));
    split_f32<<<(Dq * Dq) / 1024, 256>>>((const float4*)wo,
                                         (__nv_bfloat162*)(wh + 3 * WSZ), (__nv_bfloat162*)(wl + 3 * WSZ));

    cudaFuncSetAttribute(gemm_nt_bf<true>,  cudaFuncAttributeMaxDynamicSharedMemorySize, GEMM_SMEM);
    cudaFuncSetAttribute(gemm_nt_bf<false>, cudaFuncAttributeMaxDynamicSharedMemorySize, GEMM_SMEM);

    // Fused QKV: N = 3072 (wq|wk|wv rows are contiguous in wh/wl)
    gemm_nt_bf<true><<<dim3(3 * Dq / 256, Mq / 128), 256, GEMM_SMEM>>>(
        xh, xl, wh, wl, nullptr, qkvh, qkvl, Mq, 3 * Dq, Dq);

    transpose_v<<<dim3(Sq / 64, Bq * Hq), 256>>>(qkvh + 2 * MD, qkvl + 2 * MD, vth, vtl);

    cudaFuncSetAttribute(attn_tc, cudaFuncAttributeMaxDynamicSharedMemorySize, ATTN_SMEM);
    attn_tc<<<dim3(Sq / 128, Bq * Hq), 256, ATTN_SMEM>>>(
        qkvh, qkvl, qkvh + MD, qkvl + MD, vth, vtl, mbits, oh, ol);

    gemm_nt_bf<false><<<dim3(Dq / 256, Mq / 128), 256, GEMM_SMEM>>>(
        oh, ol, wh + 3 * WSZ, wl + 3 * WSZ, out, nullptr, nullptr, Mq, Dq, Dq);
}

// round 13
// speedup vs baseline: 1.1025x; 1.1025x over previous
#include <cuda_runtime.h>
#include <cuda_fp16.h>
#include <cstdint>
#include <cstddef>

// Problem constants
#define Bq  4
#define Sq  2048
#define Dq  1024
#define Hq  16
#define HDq 64
#define Mq  (Bq * Sq)   // 8192
#define MD  ((size_t)Mq * Dq)

// Scratch (fp16 hi/lo split pairs)
__device__ __half g_xh[MD];
__device__ __half g_xl[MD];
__device__ __half g_wh[(size_t)4 * Dq * Dq];   // wq|wk|wv|wo
__device__ __half g_wl[(size_t)4 * Dq * Dq];
__device__ __half g_qh[MD];
__device__ __half g_ql[MD];
__device__ __half g_kh[MD];
__device__ __half g_kl[MD];
__device__ __half g_vh[MD];
__device__ __half g_vl[MD];
__device__ __half g_vth[MD];                   // [B,H,HD,S]
__device__ __half g_vtl[MD];
__device__ __half g_oh[MD];                    // attention out (hi only)
__device__ unsigned int g_mbits[(size_t)Bq * Sq * (Sq / 32)];

// ---------------------------------------------------------------------------
// helpers
// ---------------------------------------------------------------------------
__device__ __forceinline__ void mma_f16(float& d0, float& d1, float& d2, float& d3,
                                        uint32_t a0, uint32_t a1, uint32_t a2, uint32_t a3,
                                        uint32_t b0, uint32_t b1)
{
    asm volatile(
        "mma.sync.aligned.m16n8k16.row.col.f32.f16.f16.f32 "
        "{%0,%1,%2,%3}, {%4,%5,%6,%7}, {%8,%9}, {%0,%1,%2,%3};"
        : "+f"(d0), "+f"(d1), "+f"(d2), "+f"(d3)
        : "r"(a0), "r"(a1), "r"(a2), "r"(a3), "r"(b0), "r"(b1));
}

__device__ __forceinline__ void ldm_x4(uint32_t& r0, uint32_t& r1, uint32_t& r2, uint32_t& r3,
                                       uint32_t addr)
{
    asm volatile("ldmatrix.sync.aligned.m8n8.x4.shared.b16 {%0,%1,%2,%3}, [%4];"
                 : "=r"(r0), "=r"(r1), "=r"(r2), "=r"(r3) : "r"(addr));
}

__device__ __forceinline__ uint32_t pack_f16(float e0, float e1)
{
    __half2 t = __floats2half2_rn(e0, e1);
    return *(uint32_t*)&t;
}

__device__ __forceinline__ void cpa16(uint32_t saddr, const void* gptr)
{
    asm volatile("cp.async.cg.shared.global [%0], [%1], 16;" :: "r"(saddr), "l"(gptr));
}
__device__ __forceinline__ void cpa_commit() { asm volatile("cp.async.commit_group;"); }
template<int N> __device__ __forceinline__ void cpa_wait()
{ asm volatile("cp.async.wait_group %0;" :: "n"(N) : "memory"); }

// ---------------------------------------------------------------------------
// fp32 -> fp16 hi/lo split
// ---------------------------------------------------------------------------
__global__ __launch_bounds__(256) void split_f32(
    const float4* __restrict__ in,
    __half2* __restrict__ hi, __half2* __restrict__ lo)
{
    size_t i = (size_t)blockIdx.x * 256 + threadIdx.x;
    float4 v = in[i];
    __half2 h0 = __floats2half2_rn(v.x, v.y);
    __half2 h1 = __floats2half2_rn(v.z, v.w);
    __half2 l0 = __floats2half2_rn(v.x - __half2float(h0.x),
                                   v.y - __half2float(h0.y));
    __half2 l1 = __floats2half2_rn(v.z - __half2float(h1.x),
                                   v.w - __half2float(h1.y));
    hi[i * 2]     = h0; hi[i * 2 + 1] = h1;
    lo[i * 2]     = l0; lo[i * 2 + 1] = l1;
}

// ---------------------------------------------------------------------------
// Tensor-core NT GEMM on pre-split fp16 hi/lo, cp.async double buffer.
// A3=true : 3-pass (AhBh + AhBl + AlBh), A needs hi+lo  (score path)
// A3=false: 2-pass (AhBh + AhBl),        A needs hi only (post-softmax path)
// BM=BN=128, BK=32, 8 warps (2x4), warp tile 64x32. F16OUT -> hi/lo fp16 out.
// ---------------------------------------------------------------------------
#define GP2B  80                      // row pitch bytes (40 halves)
#define TAB   (128 * GP2B)            // 10240 bytes per operand array

template<bool F16OUT, bool A3>
__global__ __launch_bounds__(256, 2) void gemm_nt_hf(
    const __half* __restrict__ Ahg, const __half* __restrict__ Alg,
    const __half* __restrict__ Whg, const __half* __restrict__ Wlg,
    float* __restrict__ C, __half* __restrict__ Ch, __half* __restrict__ Cl,
    int M, int N, int K)
{
    constexpr uint32_t WOFF = A3 ? 2u * TAB : 1u * TAB;     // W arrays start
    constexpr uint32_t STG  = WOFF + 2u * TAB;              // stage bytes

    extern __shared__ char smg[];
    const uint32_t sbase = (uint32_t)__cvta_generic_to_shared(smg);

    const int tid  = threadIdx.x;
    const int wid  = tid >> 5;
    const int lane = tid & 31;
    const int wm = wid >> 2;
    const int wn = wid & 3;
    const int bm = blockIdx.y * 128;
    const int bn = blockIdx.x * 128;
    const int lm  = lane >> 3;
    const int lr  = lane & 7;

    float c[4][4][4];
    #pragma unroll
    for (int i = 0; i < 4; i++)
        #pragma unroll
        for (int j = 0; j < 4; j++)
            #pragma unroll
            for (int r = 0; r < 4; r++) c[i][j][r] = 0.f;

    auto issue = [&](int k0, int stg) {
        const uint32_t sb = sbase + (uint32_t)stg * STG;
        #pragma unroll
        for (int i = 0; i < 2; i++) {
            int ch  = i * 256 + tid;        // 0..511
            int row = ch >> 2;              // 0..127
            int c16 = ch & 3;
            uint32_t so = sb + row * GP2B + c16 * 16;
            size_t ga = (size_t)(bm + row) * K + k0 + c16 * 8;
            size_t gw = (size_t)(bn + row) * K + k0 + c16 * 8;
            cpa16(so, Ahg + ga);
            if (A3) cpa16(so + TAB, Alg + ga);
            cpa16(so + WOFF,       Whg + gw);
            cpa16(so + WOFF + TAB, Wlg + gw);
        }
        cpa_commit();
    };

    issue(0, 0);
    const int T = K / 32;
    for (int t = 0; t < T; t++) {
        if (t + 1 < T) { issue((t + 1) * 32, (t + 1) & 1); cpa_wait<1>(); }
        else           { cpa_wait<0>(); }
        __syncthreads();

        const uint32_t sb = sbase + (uint32_t)(t & 1) * STG;
        const uint32_t wb = sb + WOFF;

        #pragma unroll
        for (int ks = 0; ks < 2; ks++) {
            const int a_row_in16 = lr + ((lm & 1) << 3);
            const int a_kbyte    = ks * 32 + ((lm >> 1) << 4);

            uint32_t a_hi[4][4], a_lo[4][4];
            #pragma unroll
            for (int mt = 0; mt < 4; mt++) {
                uint32_t off = (uint32_t)((wm * 64 + mt * 16 + a_row_in16) * GP2B) + a_kbyte;
                ldm_x4(a_hi[mt][0], a_hi[mt][1], a_hi[mt][2], a_hi[mt][3], sb + off);
                if (A3)
                    ldm_x4(a_lo[mt][0], a_lo[mt][1], a_lo[mt][2], a_lo[mt][3], sb + TAB + off);
            }

            uint32_t b_hi[4][2], b_lo[4][2];
            #pragma unroll
            for (int p = 0; p < 2; p++) {
                int ntile = p * 2 + (lm >> 1);
                int n_row = wn * 32 + ntile * 8 + lr;
                uint32_t off = (uint32_t)(n_row * GP2B) + (uint32_t)(ks * 32 + ((lm & 1) << 4));
                uint32_t r0, r1, r2, r3;
                ldm_x4(r0, r1, r2, r3, wb + off);
                b_hi[p * 2 + 0][0] = r0; b_hi[p * 2 + 0][1] = r1;
                b_hi[p * 2 + 1][0] = r2; b_hi[p * 2 + 1][1] = r3;
                ldm_x4(r0, r1, r2, r3, wb + TAB + off);
                b_lo[p * 2 + 0][0] = r0; b_lo[p * 2 + 0][1] = r1;
                b_lo[p * 2 + 1][0] = r2; b_lo[p * 2 + 1][1] = r3;
            }

            #pragma unroll
            for (int mt = 0; mt < 4; mt++)
                #pragma unroll
                for (int nt = 0; nt < 4; nt++) {
                    mma_f16(c[mt][nt][0], c[mt][nt][1], c[mt][nt][2], c[mt][nt][3],
                            a_hi[mt][0], a_hi[mt][1], a_hi[mt][2], a_hi[mt][3],
                            b_hi[nt][0], b_hi[nt][1]);
                    mma_f16(c[mt][nt][0], c[mt][nt][1], c[mt][nt][2], c[mt][nt][3],
                            a_hi[mt][0], a_hi[mt][1], a_hi[mt][2], a_hi[mt][3],
                            b_lo[nt][0], b_lo[nt][1]);
                    if (A3)
                        mma_f16(c[mt][nt][0], c[mt][nt][1], c[mt][nt][2], c[mt][nt][3],
                                a_lo[mt][0], a_lo[mt][1], a_lo[mt][2], a_lo[mt][3],
                                b_hi[nt][0], b_hi[nt][1]);
                }
        }
        __syncthreads();
    }

    const int g  = lane >> 2;
    const int t2 = lane & 3;
    #pragma unroll
    for (int mt = 0; mt < 4; mt++) {
        #pragma unroll
        for (int nt = 0; nt < 4; nt++) {
            int row0 = bm + wm * 64 + mt * 16 + g;
            int col  = bn + wn * 32 + nt * 8 + t2 * 2;
            if (F16OUT) {
                #pragma unroll
                for (int half = 0; half < 2; half++) {
                    float v0 = c[mt][nt][half * 2], v1 = c[mt][nt][half * 2 + 1];
                    __half2 hv = __floats2half2_rn(v0, v1);
                    __half2 lv = __floats2half2_rn(v0 - __half2float(hv.x),
                                                   v1 - __half2float(hv.y));
                    size_t off = (size_t)(row0 + half * 8) * N + col;
                    *(__half2*)(Ch + off) = hv;
                    *(__half2*)(Cl + off) = lv;
                }
            } else {
                *(float2*)(C + (size_t)row0 * N + col)       = make_float2(c[mt][nt][0], c[mt][nt][1]);
                *(float2*)(C + (size_t)(row0 + 8) * N + col) = make_float2(c[mt][nt][2], c[mt][nt][3]);
            }
        }
    }
}

// ---------------------------------------------------------------------------
// V transpose: [B,S,D] fp16 (per head [s][hd]) -> [B,H,HD,S]
// ---------------------------------------------------------------------------
__global__ __launch_bounds__(256) void transpose_v(
    const __half* __restrict__ vh, const __half* __restrict__ vl,
    __half* __restrict__ vth, __half* __restrict__ vtl)
{
    __shared__ __half th[64 * 72];
    __shared__ __half tl[64 * 72];
    const int tid = threadIdx.x;
    const int bh = blockIdx.y;
    const int b = bh >> 4, h = bh & 15;
    const int s0 = blockIdx.x * 64;

    const size_t src = (size_t)(b * Sq + s0) * Dq + h * HDq;
    #pragma unroll
    for (int i = 0; i < 2; i++) {
        int chunk = i * 256 + tid;
        int r = chunk >> 3, cc = chunk & 7;
        *(uint4*)&th[r * 72 + cc * 8] = *(const uint4*)(vh + src + (size_t)r * Dq + cc * 8);
        *(uint4*)&tl[r * 72 + cc * 8] = *(const uint4*)(vl + src + (size_t)r * Dq + cc * 8);
    }
    __syncthreads();

    const size_t dst = (size_t)bh * HDq * Sq + s0;
    #pragma unroll
    for (int i = 0; i < 2; i++) {
        int chunk = i * 256 + tid;
        int r = chunk >> 3, cc = chunk & 7;
        alignas(16) __half tmpH[8];
        alignas(16) __half tmpL[8];
        #pragma unroll
        for (int e = 0; e < 8; e++) {
            tmpH[e] = th[(cc * 8 + e) * 72 + r];
            tmpL[e] = tl[(cc * 8 + e) * 72 + r];
        }
        *(uint4*)(vth + dst + (size_t)r * Sq + cc * 8) = *(uint4*)tmpH;
        *(uint4*)(vtl + dst + (size_t)r * Sq + cc * 8) = *(uint4*)tmpL;
    }
}

// ---------------------------------------------------------------------------
// Mask pack
// ---------------------------------------------------------------------------
__global__ __launch_bounds__(256) void pack_mask(
    const unsigned int* __restrict__ mask, unsigned int* __restrict__ mbits)
{
    int w = blockIdx.x * 256 + threadIdx.x;
    size_t row = (size_t)(w >> 6);
    int wi = w & 63;
    const uint4* p = (const uint4*)(mask + row * Sq + wi * 32);
    unsigned int bits = 0;
    #pragma unroll
    for (int i = 0; i < 8; i++) {
        uint4 m = p[i];
        bits |= (unsigned)(m.x != 0u) << (4 * i + 0);
        bits |= (unsigned)(m.y != 0u) << (4 * i + 1);
        bits |= (unsigned)(m.z != 0u) << (4 * i + 2);
        bits |= (unsigned)(m.w != 0u) << (4 * i + 3);
    }
    mbits[w] = bits;
}

// ---------------------------------------------------------------------------
// Flash attention (mma.sync fp16): QK^T 3-pass, PV 2-pass (P hi only),
// epilogue writes Oh (fp16) only. cp.async double buffered.
// ---------------------------------------------------------------------------
#define APB    144
#define REG9   9216
#define STAGEB (4 * REG9)
#define ATTN_SMEM (2 * STAGEB)

__global__ __launch_bounds__(256, 2) void attn_tc(
    const __half* __restrict__ Qhg, const __half* __restrict__ Qlg,
    const __half* __restrict__ Khg, const __half* __restrict__ Klg,
    const __half* __restrict__ Vthg, const __half* __restrict__ Vtlg,
    const unsigned int* __restrict__ mbits,
    __half* __restrict__ Ohg)
{
    extern __shared__ char smem[];
    const uint32_t sbase = (uint32_t)__cvta_generic_to_shared(smem);

    const int tid  = threadIdx.x;
    const int wid  = tid >> 5;
    const int lane = tid & 31;
    const int lm   = lane >> 3;
    const int lr   = lane & 7;
    const int g    = lane >> 2;
    const int t2   = lane & 3;

    const int bh = blockIdx.y;
    const int b  = bh >> 4;
    const int h  = bh & 15;
    const int q0 = blockIdx.x * 128;

    const size_t qrow0 = (size_t)(b * Sq + q0) * Dq + h * HDq;
    #pragma unroll
    for (int i = 0; i < 4; i++) {
        int chunk = i * 256 + tid;
        int r = chunk >> 3, cc = chunk & 7;
        uint32_t so = sbase + r * APB + cc * 16;
        cpa16(so,         Qhg + qrow0 + (size_t)r * Dq + cc * 8);
        cpa16(so + 18432, Qlg + qrow0 + (size_t)r * Dq + cc * 8);
    }
    cpa_commit();
    cpa_wait<0>();
    __syncthreads();

    uint32_t qa_h[4][4], qa_l[4][4];
    {
        const int a_row = wid * 16 + lr + ((lm & 1) << 3);
        #pragma unroll
        for (int ks = 0; ks < 4; ks++) {
            uint32_t off = (uint32_t)(a_row * APB) + (uint32_t)(ks * 32 + ((lm >> 1) << 4));
            ldm_x4(qa_h[ks][0], qa_h[ks][1], qa_h[ks][2], qa_h[ks][3], sbase + off);
            ldm_x4(qa_l[ks][0], qa_l[ks][1], qa_l[ks][2], qa_l[ks][3], sbase + 18432 + off);
        }
    }
    __syncthreads();

    float o_acc[8][4];
    #pragma unroll
    for (int j = 0; j < 8; j++)
        #pragma unroll
        for (int r = 0; r < 4; r++) o_acc[j][r] = 0.f;
    float m0 = -1e30f, m1 = -1e30f, l0 = 0.f, l1 = 0.f;

    const size_t kbase  = (size_t)(b * Sq) * Dq + h * HDq;
    const size_t vtbase = (size_t)bh * HDq * Sq;
    const size_t mrow   = ((size_t)b * Sq + q0) * 64;
    const int r0 = wid * 16 + g;
    const int r1 = r0 + 8;

    {
        const uint32_t sb = sbase;
        #pragma unroll
        for (int i = 0; i < 2; i++) {
            int chunk = i * 256 + tid;
            int r = chunk >> 3, cc = chunk & 7;
            uint32_t so = sb + r * APB + cc * 16;
            size_t kq = kbase + (size_t)r * Dq + cc * 8;
            size_t vq = vtbase + (size_t)r * Sq + cc * 8;
            cpa16(so,             Khg + kq);
            cpa16(so + REG9,      Klg + kq);
            cpa16(so + 2 * REG9,  Vthg + vq);
            cpa16(so + 3 * REG9,  Vtlg + vq);
        }
        cpa_commit();
    }

    for (int t = 0; t < Sq / 64; t++) {
        const int kb = t * 64;
        __syncthreads();
        if (t + 1 < Sq / 64) {
            const uint32_t sb = sbase + (uint32_t)((t + 1) & 1) * STAGEB;
            const int kb2 = kb + 64;
            #pragma unroll
            for (int i = 0; i < 2; i++) {
                int chunk = i * 256 + tid;
                int r = chunk >> 3, cc = chunk & 7;
                uint32_t so = sb + r * APB + cc * 16;
                size_t kq = kbase + (size_t)(kb2 + r) * Dq + cc * 8;
                size_t vq = vtbase + (size_t)r * Sq + kb2 + cc * 8;
                cpa16(so,             Khg + kq);
                cpa16(so + REG9,      Klg + kq);
                cpa16(so + 2 * REG9,  Vthg + vq);
                cpa16(so + 3 * REG9,  Vtlg + vq);
            }
            cpa_commit();
            cpa_wait<1>();
        } else {
            cpa_wait<0>();
        }
        __syncthreads();

        const uint32_t kbuf = sbase + (uint32_t)(t & 1) * STAGEB;

        const uint2 mwA = *(const uint2*)(mbits + mrow + (size_t)r0 * 64 + (kb >> 5));
        const uint2 mwB = *(const uint2*)(mbits + mrow + (size_t)r1 * 64 + (kb >> 5));

        // ---- S = Q @ K^T (3-pass fp16) ----
        float s[8][4];
        #pragma unroll
        for (int j = 0; j < 8; j++)
            #pragma unroll
            for (int r = 0; r < 4; r++) s[j][r] = 0.f;

        #pragma unroll
        for (int ks = 0; ks < 4; ks++) {
            #pragma unroll
            for (int p2 = 0; p2 < 4; p2++) {
                int ntile = p2 * 2 + (lm >> 1);
                uint32_t off = (uint32_t)((ntile * 8 + lr) * APB)
                             + (uint32_t)(ks * 32 + ((lm & 1) << 4));
                uint32_t bh0, bh1, bh2, bh3, bl0, bl1, bl2, bl3;
                ldm_x4(bh0, bh1, bh2, bh3, kbuf + off);
                ldm_x4(bl0, bl1, bl2, bl3, kbuf + REG9 + off);
                int n0 = p2 * 2, n1 = p2 * 2 + 1;
                mma_f16(s[n0][0], s[n0][1], s[n0][2], s[n0][3],
                        qa_h[ks][0], qa_h[ks][1], qa_h[ks][2], qa_h[ks][3], bh0, bh1);
                mma_f16(s[n1][0], s[n1][1], s[n1][2], s[n1][3],
                        qa_h[ks][0], qa_h[ks][1], qa_h[ks][2], qa_h[ks][3], bh2, bh3);
                mma_f16(s[n0][0], s[n0][1], s[n0][2], s[n0][3],
                        qa_h[ks][0], qa_h[ks][1], qa_h[ks][2], qa_h[ks][3], bl0, bl1);
                mma_f16(s[n1][0], s[n1][1], s[n1][2], s[n1][3],
                        qa_h[ks][0], qa_h[ks][1], qa_h[ks][2], qa_h[ks][3], bl2, bl3);
                mma_f16(s[n0][0], s[n0][1], s[n0][2], s[n0][3],
                        qa_l[ks][0], qa_l[ks][1], qa_l[ks][2], qa_l[ks][3], bh0, bh1);
                mma_f16(s[n1][0], s[n1][1], s[n1][2], s[n1][3],
                        qa_l[ks][0], qa_l[ks][1], qa_l[ks][2], qa_l[ks][3], bh2, bh3);
            }
        }

        // ---- masked online softmax (warp-local) ----
        {
            unsigned int w0 = mwA.x, w1 = mwA.y;
            unsigned int x0 = mwB.x, x1 = mwB.y;
            float rmax0 = -1e30f, rmax1 = -1e30f;
            #pragma unroll
            for (int j = 0; j < 8; j++) {
                unsigned int wr0 = (j < 4) ? w0 : w1;
                unsigned int wr1 = (j < 4) ? x0 : x1;
                int sh = ((j & 3) * 8) + t2 * 2;
                bool k00 = (wr0 >> sh) & 1, k01 = (wr0 >> (sh + 1)) & 1;
                bool k10 = (wr1 >> sh) & 1, k11 = (wr1 >> (sh + 1)) & 1;
                s[j][0] = k00 ? s[j][0] * 0.125f : -1e30f;
                s[j][1] = k01 ? s[j][1] * 0.125f : -1e30f;
                s[j][2] = k10 ? s[j][2] * 0.125f : -1e30f;
                s[j][3] = k11 ? s[j][3] * 0.125f : -1e30f;
                rmax0 = fmaxf(rmax0, fmaxf(s[j][0], s[j][1]));
                rmax1 = fmaxf(rmax1, fmaxf(s[j][2], s[j][3]));
            }
            rmax0 = fmaxf(rmax0, __shfl_xor_sync(0xffffffffu, rmax0, 1));
            rmax0 = fmaxf(rmax0, __shfl_xor_sync(0xffffffffu, rmax0, 2));
            rmax1 = fmaxf(rmax1, __shfl_xor_sync(0xffffffffu, rmax1, 1));
            rmax1 = fmaxf(rmax1, __shfl_xor_sync(0xffffffffu, rmax1, 2));

            float mn0 = fmaxf(m0, rmax0);
            float mn1 = fmaxf(m1, rmax1);
            float rs0 = 0.f, rs1 = 0.f;
            #pragma unroll
            for (int j = 0; j < 8; j++) {
                s[j][0] = (s[j][0] > -1e29f) ? __expf(s[j][0] - mn0) : 0.f;
                s[j][1] = (s[j][1] > -1e29f) ? __expf(s[j][1] - mn0) : 0.f;
                s[j][2] = (s[j][2] > -1e29f) ? __expf(s[j][2] - mn1) : 0.f;
                s[j][3] = (s[j][3] > -1e29f) ? __expf(s[j][3] - mn1) : 0.f;
                rs0 += s[j][0] + s[j][1];
                rs1 += s[j][2] + s[j][3];
            }
            rs0 += __shfl_xor_sync(0xffffffffu, rs0, 1);
            rs0 += __shfl_xor_sync(0xffffffffu, rs0, 2);
            rs1 += __shfl_xor_sync(0xffffffffu, rs1, 1);
            rs1 += __shfl_xor_sync(0xffffffffu, rs1, 2);

            float al0 = __expf(m0 - mn0);
            float al1 = __expf(m1 - mn1);
            l0 = l0 * al0 + rs0; m0 = mn0;
            l1 = l1 * al1 + rs1; m1 = mn1;
            #pragma unroll
            for (int j = 0; j < 8; j++) {
                o_acc[j][0] *= al0; o_acc[j][1] *= al0;
                o_acc[j][2] *= al1; o_acc[j][3] *= al1;
            }
        }

        // ---- O += P @ V (2-pass: P hi only; V hi+lo) ----
        #pragma unroll
        for (int kk = 0; kk < 4; kk++) {
            int ja = 2 * kk, jb = 2 * kk + 1;
            uint32_t pah[4];
            pah[0] = pack_f16(s[ja][0], s[ja][1]);
            pah[1] = pack_f16(s[ja][2], s[ja][3]);
            pah[2] = pack_f16(s[jb][0], s[jb][1]);
            pah[3] = pack_f16(s[jb][2], s[jb][3]);
            #pragma unroll
            for (int p2 = 0; p2 < 4; p2++) {
                int ntile = p2 * 2 + (lm >> 1);
                uint32_t off = (uint32_t)((ntile * 8 + lr) * APB)
                             + (uint32_t)(kk * 32 + ((lm & 1) << 4));
                uint32_t bh0, bh1, bh2, bh3, bl0, bl1, bl2, bl3;
                ldm_x4(bh0, bh1, bh2, bh3, kbuf + 2 * REG9 + off);
                ldm_x4(bl0, bl1, bl2, bl3, kbuf + 3 * REG9 + off);
                int n0 = p2 * 2, n1 = p2 * 2 + 1;
                mma_f16(o_acc[n0][0], o_acc[n0][1], o_acc[n0][2], o_acc[n0][3],
                        pah[0], pah[1], pah[2], pah[3], bh0, bh1);
                mma_f16(o_acc[n1][0], o_acc[n1][1], o_acc[n1][2], o_acc[n1][3],
                        pah[0], pah[1], pah[2], pah[3], bh2, bh3);
                mma_f16(o_acc[n0][0], o_acc[n0][1], o_acc[n0][2], o_acc[n0][3],
                        pah[0], pah[1], pah[2], pah[3], bl0, bl1);
                mma_f16(o_acc[n1][0], o_acc[n1][1], o_acc[n1][2], o_acc[n1][3],
                        pah[0], pah[1], pah[2], pah[3], bl2, bl3);
            }
        }
    }

    // ---- epilogue: normalize, store Oh only ----
    const float inv0 = l0 > 0.f ? 1.f / l0 : 0.f;
    const float inv1 = l1 > 0.f ? 1.f / l1 : 0.f;
    const size_t obase = (size_t)b * Sq * Dq + (size_t)h * HDq;
    const int row0 = q0 + wid * 16 + g;
    #pragma unroll
    for (int j = 0; j < 8; j++) {
        int col = j * 8 + t2 * 2;
        #pragma unroll
        for (int half = 0; half < 2; half++) {
            float v0 = (half ? o_acc[j][2] * inv1 : o_acc[j][0] * inv0);
            float v1 = (half ? o_acc[j][3] * inv1 : o_acc[j][1] * inv0);
            __half2 hv = __floats2half2_rn(v0, v1);
            size_t off = obase + (size_t)(row0 + half * 8) * Dq + col;
            *(__half2*)(Ohg + off) = hv;
        }
    }
}

// ---------------------------------------------------------------------------
// Launch
// ---------------------------------------------------------------------------
extern "C" void kernel_launch(void* const* d_in, const int* in_sizes, int n_in,
                              void* d_out, int out_size)
{
    const float* x  = (const float*)d_in[0];
    const unsigned int* mask = (const unsigned int*)d_in[1];
    const float* wq = (const float*)d_in[2];
    const float* wk = (const float*)d_in[3];
    const float* wv = (const float*)d_in[4];
    const float* wo = (const float*)d_in[5];
    float* out = (float*)d_out;

    __half *xh, *xl, *wh, *wl, *qh, *ql, *kh, *kl, *vh, *vl, *vth, *vtl, *oh;
    unsigned int* mbits;
    cudaGetSymbolAddress((void**)&xh,  g_xh);
    cudaGetSymbolAddress((void**)&xl,  g_xl);
    cudaGetSymbolAddress((void**)&wh,  g_wh);
    cudaGetSymbolAddress((void**)&wl,  g_wl);
    cudaGetSymbolAddress((void**)&qh,  g_qh);
    cudaGetSymbolAddress((void**)&ql,  g_ql);
    cudaGetSymbolAddress((void**)&kh,  g_kh);
    cudaGetSymbolAddress((void**)&kl,  g_kl);
    cudaGetSymbolAddress((void**)&vh,  g_vh);
    cudaGetSymbolAddress((void**)&vl,  g_vl);
    cudaGetSymbolAddress((void**)&vth, g_vth);
    cudaGetSymbolAddress((void**)&vtl, g_vtl);
    cudaGetSymbolAddress((void**)&oh,  g_oh);
    cudaGetSymbolAddress((void**)&mbits, g_mbits);

    const size_t WSZ = (size_t)Dq * Dq;

    pack_mask<<<(Bq * Sq * (Sq / 32)) / 256, 256>>>(mask, mbits);
    split_f32<<<(Mq * Dq) / 1024, 256>>>((const float4*)x,  (__half2*)xh, (__half2*)xl);
    split_f32<<<(Dq * Dq) / 1024, 256>>>((const float4*)wq, (__half2*)(wh + 0 * WSZ), (__half2*)(wl + 0 * WSZ));
    split_f32<<<(Dq * Dq) / 1024, 256>>>((const float4*)wk, (__half2*)(wh + 1 * WSZ), (__half2*)(wl + 1 * WSZ));
    split_f32<<<(Dq * Dq) / 1024, 256>>>((const float4*)wv, (__half2*)(wh + 2 * WSZ), (__half2*)(wl + 2 * WSZ));
    split_f32<<<(Dq * Dq) / 1024, 256>>>((const float4*)wo, (__half2*)(wh + 3 * WSZ), (__half2*)(wl + 3 * WSZ));

    const int SM3 = 2 * (4 * TAB);   // 81920: 3-pass stage x2
    const int SM2 = 2 * (3 * TAB);   // 61440: 2-pass stage x2
    cudaFuncSetAttribute(gemm_nt_hf<true,  true>,  cudaFuncAttributeMaxDynamicSharedMemorySize, SM3);
    cudaFuncSetAttribute(gemm_nt_hf<false, false>, cudaFuncAttributeMaxDynamicSharedMemorySize, SM2);

    dim3 gp(Dq / 128, Mq / 128);
    gemm_nt_hf<true, true><<<gp, 256, SM3>>>(xh, xl, wh + 0 * WSZ, wl + 0 * WSZ,
                                             nullptr, qh, ql, Mq, Dq, Dq);
    gemm_nt_hf<true, true><<<gp, 256, SM3>>>(xh, xl, wh + 1 * WSZ, wl + 1 * WSZ,
                                             nullptr, kh, kl, Mq, Dq, Dq);
    gemm_nt_hf<true, true><<<gp, 256, SM3>>>(xh, xl, wh + 2 * WSZ, wl + 2 * WSZ,
                                             nullptr, vh, vl, Mq, Dq, Dq);

    transpose_v<<<dim3(Sq / 64, Bq * Hq), 256>>>(vh, vl, vth, vtl);

    cudaFuncSetAttribute(attn_tc, cudaFuncAttributeMaxDynamicSharedMemorySize, ATTN_SMEM);
    attn_tc<<<dim3(Sq / 128, Bq * Hq), 256, ATTN_SMEM>>>(qh, ql, kh, kl, vth, vtl, mbits, oh);

    gemm_nt_hf<false, false><<<gp, 256, SM2>>>(oh, nullptr, wh + 3 * WSZ, wl + 3 * WSZ,
                                               out, nullptr, nullptr, Mq, Dq, Dq);
}

// round 15
// speedup vs baseline: 1.3030x; 1.1819x over previous
#include <cuda_runtime.h>
#include <cuda_fp16.h>
#include <cstdint>
#include <cstddef>

// Problem constants
#define Bq  4
#define Sq  2048
#define Dq  1024
#define Hq  16
#define HDq 64
#define Mq  (Bq * Sq)   // 8192
#define MD  ((size_t)Mq * Dq)

// Scratch
__device__ __half g_xh[MD];
__device__ __half g_xl[MD];
__device__ __half g_wh[(size_t)4 * Dq * Dq];   // wq|wk|wv|wo
__device__ __half g_wl[(size_t)4 * Dq * Dq];
__device__ __half g_qh[MD];
__device__ __half g_ql[MD];
__device__ __half g_kh[MD];                    // K: hi only
__device__ __half g_vh[MD];                    // V: hi only
__device__ __half g_vth[MD];                   // [B,H,HD,S] hi only
__device__ __half g_oh[MD];                    // attention out (hi only)
__device__ unsigned int g_mbits[(size_t)Bq * Sq * (Sq / 32)];

// ---------------------------------------------------------------------------
// helpers
// ---------------------------------------------------------------------------
__device__ __forceinline__ void mma_f16(float& d0, float& d1, float& d2, float& d3,
                                        uint32_t a0, uint32_t a1, uint32_t a2, uint32_t a3,
                                        uint32_t b0, uint32_t b1)
{
    asm volatile(
        "mma.sync.aligned.m16n8k16.row.col.f32.f16.f16.f32 "
        "{%0,%1,%2,%3}, {%4,%5,%6,%7}, {%8,%9}, {%0,%1,%2,%3};"
        : "+f"(d0), "+f"(d1), "+f"(d2), "+f"(d3)
        : "r"(a0), "r"(a1), "r"(a2), "r"(a3), "r"(b0), "r"(b1));
}

__device__ __forceinline__ void ldm_x4(uint32_t& r0, uint32_t& r1, uint32_t& r2, uint32_t& r3,
                                       uint32_t addr)
{
    asm volatile("ldmatrix.sync.aligned.m8n8.x4.shared.b16 {%0,%1,%2,%3}, [%4];"
                 : "=r"(r0), "=r"(r1), "=r"(r2), "=r"(r3) : "r"(addr));
}

__device__ __forceinline__ uint32_t pack_f16(float e0, float e1)
{
    __half2 t = __floats2half2_rn(e0, e1);
    return *(uint32_t*)&t;
}

__device__ __forceinline__ void cpa16(uint32_t saddr, const void* gptr)
{
    asm volatile("cp.async.cg.shared.global [%0], [%1], 16;" :: "r"(saddr), "l"(gptr));
}
__device__ __forceinline__ void cpa_commit() { asm volatile("cp.async.commit_group;"); }
template<int N> __device__ __forceinline__ void cpa_wait()
{ asm volatile("cp.async.wait_group %0;" :: "n"(N) : "memory"); }

// ---------------------------------------------------------------------------
// fp32 -> fp16 hi/lo split
// ---------------------------------------------------------------------------
__global__ __launch_bounds__(256) void split_f32(
    const float4* __restrict__ in,
    __half2* __restrict__ hi, __half2* __restrict__ lo)
{
    size_t i = (size_t)blockIdx.x * 256 + threadIdx.x;
    float4 v = in[i];
    __half2 h0 = __floats2half2_rn(v.x, v.y);
    __half2 h1 = __floats2half2_rn(v.z, v.w);
    __half2 l0 = __floats2half2_rn(v.x - __half2float(h0.x),
                                   v.y - __half2float(h0.y));
    __half2 l1 = __floats2half2_rn(v.z - __half2float(h1.x),
                                   v.w - __half2float(h1.y));
    hi[i * 2]     = h0; hi[i * 2 + 1] = h1;
    lo[i * 2]     = l0; lo[i * 2 + 1] = l1;
}

// ---------------------------------------------------------------------------
// Tensor-core NT GEMM on pre-split fp16 hi/lo, cp.async double buffer.
// A3=true : 3-pass (AhBh + AhBl + AlBh); A3=false: 2-pass (AhBh + AhBl).
// OMODE: 0 = fp32 C, 1 = fp16 hi+lo, 2 = fp16 hi only.
// BM=BN=128, BK=32, 8 warps (2x4), warp tile 64x32.
// ---------------------------------------------------------------------------
#define GP2B  80                      // row pitch bytes (40 halves)
#define TAB   (128 * GP2B)            // 10240 bytes per operand array

template<int OMODE, bool A3>
__global__ __launch_bounds__(256, 2) void gemm_nt_hf(
    const __half* __restrict__ Ahg, const __half* __restrict__ Alg,
    const __half* __restrict__ Whg, const __half* __restrict__ Wlg,
    float* __restrict__ C, __half* __restrict__ Ch, __half* __restrict__ Cl,
    int M, int N, int K)
{
    constexpr uint32_t WOFF = A3 ? 2u * TAB : 1u * TAB;
    constexpr uint32_t STG  = WOFF + 2u * TAB;

    extern __shared__ char smg[];
    const uint32_t sbase = (uint32_t)__cvta_generic_to_shared(smg);

    const int tid  = threadIdx.x;
    const int wid  = tid >> 5;
    const int lane = tid & 31;
    const int wm = wid >> 2;
    const int wn = wid & 3;
    const int bm = blockIdx.y * 128;
    const int bn = blockIdx.x * 128;
    const int lm  = lane >> 3;
    const int lr  = lane & 7;

    float c[4][4][4];
    #pragma unroll
    for (int i = 0; i < 4; i++)
        #pragma unroll
        for (int j = 0; j < 4; j++)
            #pragma unroll
            for (int r = 0; r < 4; r++) c[i][j][r] = 0.f;

    auto issue = [&](int k0, int stg) {
        const uint32_t sb = sbase + (uint32_t)stg * STG;
        #pragma unroll
        for (int i = 0; i < 2; i++) {
            int ch  = i * 256 + tid;
            int row = ch >> 2;
            int c16 = ch & 3;
            uint32_t so = sb + row * GP2B + c16 * 16;
            size_t ga = (size_t)(bm + row) * K + k0 + c16 * 8;
            size_t gw = (size_t)(bn + row) * K + k0 + c16 * 8;
            cpa16(so, Ahg + ga);
            if (A3) cpa16(so + TAB, Alg + ga);
            cpa16(so + WOFF,       Whg + gw);
            cpa16(so + WOFF + TAB, Wlg + gw);
        }
        cpa_commit();
    };

    issue(0, 0);
    const int T = K / 32;
    for (int t = 0; t < T; t++) {
        if (t + 1 < T) { issue((t + 1) * 32, (t + 1) & 1); cpa_wait<1>(); }
        else           { cpa_wait<0>(); }
        __syncthreads();

        const uint32_t sb = sbase + (uint32_t)(t & 1) * STG;
        const uint32_t wb = sb + WOFF;

        #pragma unroll
        for (int ks = 0; ks < 2; ks++) {
            const int a_row_in16 = lr + ((lm & 1) << 3);
            const int a_kbyte    = ks * 32 + ((lm >> 1) << 4);

            uint32_t a_hi[4][4], a_lo[4][4];
            #pragma unroll
            for (int mt = 0; mt < 4; mt++) {
                uint32_t off = (uint32_t)((wm * 64 + mt * 16 + a_row_in16) * GP2B) + a_kbyte;
                ldm_x4(a_hi[mt][0], a_hi[mt][1], a_hi[mt][2], a_hi[mt][3], sb + off);
                if (A3)
                    ldm_x4(a_lo[mt][0], a_lo[mt][1], a_lo[mt][2], a_lo[mt][3], sb + TAB + off);
            }

            uint32_t b_hi[4][2], b_lo[4][2];
            #pragma unroll
            for (int p = 0; p < 2; p++) {
                int ntile = p * 2 + (lm >> 1);
                int n_row = wn * 32 + ntile * 8 + lr;
                uint32_t off = (uint32_t)(n_row * GP2B) + (uint32_t)(ks * 32 + ((lm & 1) << 4));
                uint32_t r0, r1, r2, r3;
                ldm_x4(r0, r1, r2, r3, wb + off);
                b_hi[p * 2 + 0][0] = r0; b_hi[p * 2 + 0][1] = r1;
                b_hi[p * 2 + 1][0] = r2; b_hi[p * 2 + 1][1] = r3;
                ldm_x4(r0, r1, r2, r3, wb + TAB + off);
                b_lo[p * 2 + 0][0] = r0; b_lo[p * 2 + 0][1] = r1;
                b_lo[p * 2 + 1][0] = r2; b_lo[p * 2 + 1][1] = r3;
            }

            #pragma unroll
            for (int mt = 0; mt < 4; mt++)
                #pragma unroll
                for (int nt = 0; nt < 4; nt++) {
                    mma_f16(c[mt][nt][0], c[mt][nt][1], c[mt][nt][2], c[mt][nt][3],
                            a_hi[mt][0], a_hi[mt][1], a_hi[mt][2], a_hi[mt][3],
                            b_hi[nt][0], b_hi[nt][1]);
                    mma_f16(c[mt][nt][0], c[mt][nt][1], c[mt][nt][2], c[mt][nt][3],
                            a_hi[mt][0], a_hi[mt][1], a_hi[mt][2], a_hi[mt][3],
                            b_lo[nt][0], b_lo[nt][1]);
                    if (A3)
                        mma_f16(c[mt][nt][0], c[mt][nt][1], c[mt][nt][2], c[mt][nt][3],
                                a_lo[mt][0], a_lo[mt][1], a_lo[mt][2], a_lo[mt][3],
                                b_hi[nt][0], b_hi[nt][1]);
                }
        }
        __syncthreads();
    }

    const int g  = lane >> 2;
    const int t2 = lane & 3;
    #pragma unroll
    for (int mt = 0; mt < 4; mt++) {
        #pragma unroll
        for (int nt = 0; nt < 4; nt++) {
            int row0 = bm + wm * 64 + mt * 16 + g;
            int col  = bn + wn * 32 + nt * 8 + t2 * 2;
            #pragma unroll
            for (int half = 0; half < 2; half++) {
                float v0 = c[mt][nt][half * 2], v1 = c[mt][nt][half * 2 + 1];
                size_t off = (size_t)(row0 + half * 8) * N + col;
                if (OMODE == 0) {
                    *(float2*)(C + off) = make_float2(v0, v1);
                } else {
                    __half2 hv = __floats2half2_rn(v0, v1);
                    *(__half2*)(Ch + off) = hv;
                    if (OMODE == 1) {
                        __half2 lv = __floats2half2_rn(v0 - __half2float(hv.x),
                                                       v1 - __half2float(hv.y));
                        *(__half2*)(Cl + off) = lv;
                    }
                }
            }
        }
    }
}

// ---------------------------------------------------------------------------
// V transpose (hi only): [B,S,D] (per head [s][hd]) -> [B,H,HD,S]
// ---------------------------------------------------------------------------
__global__ __launch_bounds__(256) void transpose_v(
    const __half* __restrict__ vh, __half* __restrict__ vth)
{
    __shared__ __half th[64 * 72];
    const int tid = threadIdx.x;
    const int bh = blockIdx.y;
    const int b = bh >> 4, h = bh & 15;
    const int s0 = blockIdx.x * 64;

    const size_t src = (size_t)(b * Sq + s0) * Dq + h * HDq;
    #pragma unroll
    for (int i = 0; i < 2; i++) {
        int chunk = i * 256 + tid;
        int r = chunk >> 3, cc = chunk & 7;
        *(uint4*)&th[r * 72 + cc * 8] = *(const uint4*)(vh + src + (size_t)r * Dq + cc * 8);
    }
    __syncthreads();

    const size_t dst = (size_t)bh * HDq * Sq + s0;
    #pragma unroll
    for (int i = 0; i < 2; i++) {
        int chunk = i * 256 + tid;
        int r = chunk >> 3, cc = chunk & 7;
        alignas(16) __half tmpH[8];
        #pragma unroll
        for (int e = 0; e < 8; e++)
            tmpH[e] = th[(cc * 8 + e) * 72 + r];
        *(uint4*)(vth + dst + (size_t)r * Sq + cc * 8) = *(uint4*)tmpH;
    }
}

// ---------------------------------------------------------------------------
// Mask pack
// ---------------------------------------------------------------------------
__global__ __launch_bounds__(256) void pack_mask(
    const unsigned int* __restrict__ mask, unsigned int* __restrict__ mbits)
{
    int w = blockIdx.x * 256 + threadIdx.x;
    size_t row = (size_t)(w >> 6);
    int wi = w & 63;
    const uint4* p = (const uint4*)(mask + row * Sq + wi * 32);
    unsigned int bits = 0;
    #pragma unroll
    for (int i = 0; i < 8; i++) {
        uint4 m = p[i];
        bits |= (unsigned)(m.x != 0u) << (4 * i + 0);
        bits |= (unsigned)(m.y != 0u) << (4 * i + 1);
        bits |= (unsigned)(m.z != 0u) << (4 * i + 2);
        bits |= (unsigned)(m.w != 0u) << (4 * i + 3);
    }
    mbits[w] = bits;
}

// ---------------------------------------------------------------------------
// Flash attention: S = (Qh+Ql)@Kh^T (2 mma), PV = Ph@Vh (1 mma pass).
// K/V hi-only in smem; cp.async double buffered (18KB/stage).
// ---------------------------------------------------------------------------
#define APB    144
#define REG9   9216
#define STAGEB (2 * REG9)             // Kh | Vth
#define ATTN_SMEM (2 * STAGEB)        // 36864

__global__ __launch_bounds__(256, 2) void attn_tc(
    const __half* __restrict__ Qhg, const __half* __restrict__ Qlg,
    const __half* __restrict__ Khg,
    const __half* __restrict__ Vthg,
    const unsigned int* __restrict__ mbits,
    __half* __restrict__ Ohg)
{
    extern __shared__ char smem[];
    const uint32_t sbase = (uint32_t)__cvta_generic_to_shared(smem);

    const int tid  = threadIdx.x;
    const int wid  = tid >> 5;
    const int lane = tid & 31;
    const int lm   = lane >> 3;
    const int lr   = lane & 7;
    const int g    = lane >> 2;
    const int t2   = lane & 3;

    const int bh = blockIdx.y;
    const int b  = bh >> 4;
    const int h  = bh & 15;
    const int q0 = blockIdx.x * 128;

    // stage Q hi/lo into the two stage buffers temporarily
    const size_t qrow0 = (size_t)(b * Sq + q0) * Dq + h * HDq;
    #pragma unroll
    for (int i = 0; i < 4; i++) {
        int chunk = i * 256 + tid;
        int r = chunk >> 3, cc = chunk & 7;
        uint32_t so = sbase + r * APB + cc * 16;
        cpa16(so,          Qhg + qrow0 + (size_t)r * Dq + cc * 8);
        cpa16(so + STAGEB, Qlg + qrow0 + (size_t)r * Dq + cc * 8);
    }
    cpa_commit();
    cpa_wait<0>();
    __syncthreads();

    uint32_t qa_h[4][4], qa_l[4][4];
    {
        const int a_row = wid * 16 + lr + ((lm & 1) << 3);
        #pragma unroll
        for (int ks = 0; ks < 4; ks++) {
            uint32_t off = (uint32_t)(a_row * APB) + (uint32_t)(ks * 32 + ((lm >> 1) << 4));
            ldm_x4(qa_h[ks][0], qa_h[ks][1], qa_h[ks][2], qa_h[ks][3], sbase + off);
            ldm_x4(qa_l[ks][0], qa_l[ks][1], qa_l[ks][2], qa_l[ks][3], sbase + STAGEB + off);
        }
    }
    __syncthreads();

    float o_acc[8][4];
    #pragma unroll
    for (int j = 0; j < 8; j++)
        #pragma unroll
        for (int r = 0; r < 4; r++) o_acc[j][r] = 0.f;
    float m0 = -1e30f, m1 = -1e30f, l0 = 0.f, l1 = 0.f;

    const size_t kbase  = (size_t)(b * Sq) * Dq + h * HDq;
    const size_t vtbase = (size_t)bh * HDq * Sq;
    const size_t mrow   = ((size_t)b * Sq + q0) * 64;
    const int r0 = wid * 16 + g;
    const int r1 = r0 + 8;

    {
        const uint32_t sb = sbase;
        #pragma unroll
        for (int i = 0; i < 2; i++) {
            int chunk = i * 256 + tid;
            int r = chunk >> 3, cc = chunk & 7;
            uint32_t so = sb + r * APB + cc * 16;
            cpa16(so,        Khg  + kbase  + (size_t)r * Dq + cc * 8);
            cpa16(so + REG9, Vthg + vtbase + (size_t)r * Sq + cc * 8);
        }
        cpa_commit();
    }

    for (int t = 0; t < Sq / 64; t++) {
        const int kb = t * 64;
        __syncthreads();
        if (t + 1 < Sq / 64) {
            const uint32_t sb = sbase + (uint32_t)((t + 1) & 1) * STAGEB;
            const int kb2 = kb + 64;
            #pragma unroll
            for (int i = 0; i < 2; i++) {
                int chunk = i * 256 + tid;
                int r = chunk >> 3, cc = chunk & 7;
                uint32_t so = sb + r * APB + cc * 16;
                cpa16(so,        Khg  + kbase  + (size_t)(kb2 + r) * Dq + cc * 8);
                cpa16(so + REG9, Vthg + vtbase + (size_t)r * Sq + kb2 + cc * 8);
            }
            cpa_commit();
            cpa_wait<1>();
        } else {
            cpa_wait<0>();
        }
        __syncthreads();

        const uint32_t kbuf = sbase + (uint32_t)(t & 1) * STAGEB;

        const uint2 mwA = *(const uint2*)(mbits + mrow + (size_t)r0 * 64 + (kb >> 5));
        const uint2 mwB = *(const uint2*)(mbits + mrow + (size_t)r1 * 64 + (kb >> 5));

        // ---- S = (Qh + Ql) @ Kh^T ----
        float s[8][4];
        #pragma unroll
        for (int j = 0; j < 8; j++)
            #pragma unroll
            for (int r = 0; r < 4; r++) s[j][r] = 0.f;

        #pragma unroll
        for (int ks = 0; ks < 4; ks++) {
            #pragma unroll
            for (int p2 = 0; p2 < 4; p2++) {
                int ntile = p2 * 2 + (lm >> 1);
                uint32_t off = (uint32_t)((ntile * 8 + lr) * APB)
                             + (uint32_t)(ks * 32 + ((lm & 1) << 4));
                uint32_t bh0, bh1, bh2, bh3;
                ldm_x4(bh0, bh1, bh2, bh3, kbuf + off);
                int n0 = p2 * 2, n1 = p2 * 2 + 1;
                mma_f16(s[n0][0], s[n0][1], s[n0][2], s[n0][3],
                        qa_h[ks][0], qa_h[ks][1], qa_h[ks][2], qa_h[ks][3], bh0, bh1);
                mma_f16(s[n1][0], s[n1][1], s[n1][2], s[n1][3],
                        qa_h[ks][0], qa_h[ks][1], qa_h[ks][2], qa_h[ks][3], bh2, bh3);
                mma_f16(s[n0][0], s[n0][1], s[n0][2], s[n0][3],
                        qa_l[ks][0], qa_l[ks][1], qa_l[ks][2], qa_l[ks][3], bh0, bh1);
                mma_f16(s[n1][0], s[n1][1], s[n1][2], s[n1][3],
                        qa_l[ks][0], qa_l[ks][1], qa_l[ks][2], qa_l[ks][3], bh2, bh3);
            }
        }

        // ---- masked online softmax (warp-local) ----
        {
            unsigned int w0 = mwA.x, w1 = mwA.y;
            unsigned int x0 = mwB.x, x1 = mwB.y;
            float rmax0 = -1e30f, rmax1 = -1e30f;
            #pragma unroll
            for (int j = 0; j < 8; j++) {
                unsigned int wr0 = (j < 4) ? w0 : w1;
                unsigned int wr1 = (j < 4) ? x0 : x1;
                int sh = ((j & 3) * 8) + t2 * 2;
                bool k00 = (wr0 >> sh) & 1, k01 = (wr0 >> (sh + 1)) & 1;
                bool k10 = (wr1 >> sh) & 1, k11 = (wr1 >> (sh + 1)) & 1;
                s[j][0] = k00 ? s[j][0] * 0.125f : -1e30f;
                s[j][1] = k01 ? s[j][1] * 0.125f : -1e30f;
                s[j][2] = k10 ? s[j][2] * 0.125f : -1e30f;
                s[j][3] = k11 ? s[j][3] * 0.125f : -1e30f;
                rmax0 = fmaxf(rmax0, fmaxf(s[j][0], s[j][1]));
                rmax1 = fmaxf(rmax1, fmaxf(s[j][2], s[j][3]));
            }
            rmax0 = fmaxf(rmax0, __shfl_xor_sync(0xffffffffu, rmax0, 1));
            rmax0 = fmaxf(rmax0, __shfl_xor_sync(0xffffffffu, rmax0, 2));
            rmax1 = fmaxf(rmax1, __shfl_xor_sync(0xffffffffu, rmax1, 1));
            rmax1 = fmaxf(rmax1, __shfl_xor_sync(0xffffffffu, rmax1, 2));

            float mn0 = fmaxf(m0, rmax0);
            float mn1 = fmaxf(m1, rmax1);
            float rs0 = 0.f, rs1 = 0.f;
            #pragma unroll
            for (int j = 0; j < 8; j++) {
                s[j][0] = (s[j][0] > -1e29f) ? __expf(s[j][0] - mn0) : 0.f;
                s[j][1] = (s[j][1] > -1e29f) ? __expf(s[j][1] - mn0) : 0.f;
                s[j][2] = (s[j][2] > -1e29f) ? __expf(s[j][2] - mn1) : 0.f;
                s[j][3] = (s[j][3] > -1e29f) ? __expf(s[j][3] - mn1) : 0.f;
                rs0 += s[j][0] + s[j][1];
                rs1 += s[j][2] + s[j][3];
            }
            rs0 += __shfl_xor_sync(0xffffffffu, rs0, 1);
            rs0 += __shfl_xor_sync(0xffffffffu, rs0, 2);
            rs1 += __shfl_xor_sync(0xffffffffu, rs1, 1);
            rs1 += __shfl_xor_sync(0xffffffffu, rs1, 2);

            float al0 = __expf(m0 - mn0);
            float al1 = __expf(m1 - mn1);
            l0 = l0 * al0 + rs0; m0 = mn0;
            l1 = l1 * al1 + rs1; m1 = mn1;
            #pragma unroll
            for (int j = 0; j < 8; j++) {
                o_acc[j][0] *= al0; o_acc[j][1] *= al0;
                o_acc[j][2] *= al1; o_acc[j][3] *= al1;
            }
        }

        // ---- O += Ph @ Vh ----
        #pragma unroll
        for (int kk = 0; kk < 4; kk++) {
            int ja = 2 * kk, jb = 2 * kk + 1;
            uint32_t pah[4];
            pah[0] = pack_f16(s[ja][0], s[ja][1]);
            pah[1] = pack_f16(s[ja][2], s[ja][3]);
            pah[2] = pack_f16(s[jb][0], s[jb][1]);
            pah[3] = pack_f16(s[jb][2], s[jb][3]);
            #pragma unroll
            for (int p2 = 0; p2 < 4; p2++) {
                int ntile = p2 * 2 + (lm >> 1);
                uint32_t off = (uint32_t)((ntile * 8 + lr) * APB)
                             + (uint32_t)(kk * 32 + ((lm & 1) << 4));
                uint32_t bh0, bh1, bh2, bh3;
                ldm_x4(bh0, bh1, bh2, bh3, kbuf + REG9 + off);
                int n0 = p2 * 2, n1 = p2 * 2 + 1;
                mma_f16(o_acc[n0][0], o_acc[n0][1], o_acc[n0][2], o_acc[n0][3],
                        pah[0], pah[1], pah[2], pah[3], bh0, bh1);
                mma_f16(o_acc[n1][0], o_acc[n1][1], o_acc[n1][2], o_acc[n1][3],
                        pah[0], pah[1], pah[2], pah[3], bh2, bh3);
            }
        }
    }

    // ---- epilogue: normalize, store Oh ----
    const float inv0 = l0 > 0.f ? 1.f / l0 : 0.f;
    const float inv1 = l1 > 0.f ? 1.f / l1 : 0.f;
    const size_t obase = (size_t)b * Sq * Dq + (size_t)h * HDq;
    const int row0 = q0 + wid * 16 + g;
    #pragma unroll
    for (int j = 0; j < 8; j++) {
        int col = j * 8 + t2 * 2;
        #pragma unroll
        for (int half = 0; half < 2; half++) {
            float v0 = (half ? o_acc[j][2] * inv1 : o_acc[j][0] * inv0);
            float v1 = (half ? o_acc[j][3] * inv1 : o_acc[j][1] * inv0);
            __half2 hv = __floats2half2_rn(v0, v1);
            size_t off = obase + (size_t)(row0 + half * 8) * Dq + col;
            *(__half2*)(Ohg + off) = hv;
        }
    }
}

// ---------------------------------------------------------------------------
// Launch
// ---------------------------------------------------------------------------
extern "C" void kernel_launch(void* const* d_in, const int* in_sizes, int n_in,
                              void* d_out, int out_size)
{
    const float* x  = (const float*)d_in[0];
    const unsigned int* mask = (const unsigned int*)d_in[1];
    const float* wq = (const float*)d_in[2];
    const float* wk = (const float*)d_in[3];
    const float* wv = (const float*)d_in[4];
    const float* wo = (const float*)d_in[5];
    float* out = (float*)d_out;

    __half *xh, *xl, *wh, *wl, *qh, *ql, *kh, *vh, *vth, *oh;
    unsigned int* mbits;
    cudaGetSymbolAddress((void**)&xh,  g_xh);
    cudaGetSymbolAddress((void**)&xl,  g_xl);
    cudaGetSymbolAddress((void**)&wh,  g_wh);
    cudaGetSymbolAddress((void**)&wl,  g_wl);
    cudaGetSymbolAddress((void**)&qh,  g_qh);
    cudaGetSymbolAddress((void**)&ql,  g_ql);
    cudaGetSymbolAddress((void**)&kh,  g_kh);
    cudaGetSymbolAddress((void**)&vh,  g_vh);
    cudaGetSymbolAddress((void**)&vth, g_vth);
    cudaGetSymbolAddress((void**)&oh,  g_oh);
    cudaGetSymbolAddress((void**)&mbits, g_mbits);

    const size_t WSZ = (size_t)Dq * Dq;

    pack_mask<<<(Bq * Sq * (Sq / 32)) / 256, 256>>>(mask, mbits);
    split_f32<<<(Mq * Dq) / 1024, 256>>>((const float4*)x,  (__half2*)xh, (__half2*)xl);
    split_f32<<<(Dq * Dq) / 1024, 256>>>((const float4*)wq, (__half2*)(wh + 0 * WSZ), (__half2*)(wl + 0 * WSZ));
    split_f32<<<(Dq * Dq) / 1024, 256>>>((const float4*)wk, (__half2*)(wh + 1 * WSZ), (__half2*)(wl + 1 * WSZ));
    split_f32<<<(Dq * Dq) / 1024, 256>>>((const float4*)wv, (__half2*)(wh + 2 * WSZ), (__half2*)(wl + 2 * WSZ));
    split_f32<<<(Dq * Dq) / 1024, 256>>>((const float4*)wo, (__half2*)(wh + 3 * WSZ), (__half2*)(wl + 3 * WSZ));

    const int SM3 = 2 * (4 * TAB);   // 81920: 3-pass stage x2
    const int SM2 = 2 * (3 * TAB);   // 61440: 2-pass stage x2
    cudaFuncSetAttribute(gemm_nt_hf<1, true>,  cudaFuncAttributeMaxDynamicSharedMemorySize, SM3);
    cudaFuncSetAttribute(gemm_nt_hf<2, true>,  cudaFuncAttributeMaxDynamicSharedMemorySize, SM3);
    cudaFuncSetAttribute(gemm_nt_hf<0, false>, cudaFuncAttributeMaxDynamicSharedMemorySize, SM2);

    dim3 gp(Dq / 128, Mq / 128);
    gemm_nt_hf<1, true><<<gp, 256, SM3>>>(xh, xl, wh + 0 * WSZ, wl + 0 * WSZ,
                                          nullptr, qh, ql, Mq, Dq, Dq);
    gemm_nt_hf<2, true><<<gp, 256, SM3>>>(xh, xl, wh + 1 * WSZ, wl + 1 * WSZ,
                                          nullptr, kh, nullptr, Mq, Dq, Dq);
    gemm_nt_hf<2, true><<<gp, 256, SM3>>>(xh, xl, wh + 2 * WSZ, wl + 2 * WSZ,
                                          nullptr, vh, nullptr, Mq, Dq, Dq);

    transpose_v<<<dim3(Sq / 64, Bq * Hq), 256>>>(vh, vth);

    cudaFuncSetAttribute(attn_tc, cudaFuncAttributeMaxDynamicSharedMemorySize, ATTN_SMEM);
    attn_tc<<<dim3(Sq / 128, Bq * Hq), 256, ATTN_SMEM>>>(qh, ql, kh, vth, mbits, oh);

    gemm_nt_hf<0, false><<<gp, 256, SM2>>>(oh, nullptr, wh + 3 * WSZ, wl + 3 * WSZ,
                                           out, nullptr, nullptr, Mq, Dq, Dq);
}